// round 5
// baseline (speedup 1.0000x reference)
#include <cuda_runtime.h>

#define N_USERS 200000
#define N_SPOTS 50000
#define D 64
#define DV 16           // D/4 float4 per row
#define MAX_E 3200000
#define CHUNK 512

// ---------------- __device__ scratch (no allocations allowed) ----------------
__device__ int   g_deg_user[N_USERS];
__device__ int   g_deg_spot[N_SPOTS];
__device__ float g_inv_user[N_USERS];
__device__ float g_inv_spot[N_SPOTS];
__device__ int   g_start_user[N_USERS + 1];
__device__ int   g_start_spot[N_SPOTS + 1];
__device__ int   g_adj_user[MAX_E];   // spot neighbors grouped by user
__device__ int   g_adj_spot[MAX_E];   // user neighbors grouped by spot
__device__ int   g_rank_user[MAX_E];  // edge rank within its user's list
__device__ int   g_rank_spot[MAX_E];  // edge rank within its spot's list
__device__ int   g_csum_user[CHUNK];  // chunk partial sums (<=391 used)
__device__ int   g_csum_spot[CHUNK];  // (<=98 used)

// ---------------- init: zero degree counters ----------------
__global__ void init_kernel() {
    int stride = gridDim.x * blockDim.x;
    int i = blockIdx.x * blockDim.x + threadIdx.x;
    for (int j = i; j < N_USERS; j += stride) g_deg_user[j] = 0;
    for (int j = i; j < N_SPOTS; j += stride) g_deg_spot[j] = 0;
}

// ---------------- degree count + per-edge rank ----------------
__global__ void degree_rank_kernel(const int* __restrict__ ui,
                                   const int* __restrict__ si, int E) {
    int e = blockIdx.x * blockDim.x + threadIdx.x;
    if (e < E) {
        g_rank_user[e] = atomicAdd(&g_deg_user[ui[e]], 1);
        g_rank_spot[e] = atomicAdd(&g_deg_spot[si[e]], 1);
    }
}

// ---------------- scan phase 1: per-chunk sums (+ fused inv = rsqrt(deg)) ----
__global__ void chunk_sum_kernel(const int* __restrict__ deg,
                                 int* __restrict__ sums,
                                 float* __restrict__ inv, int n) {
    __shared__ int sm[CHUNK];
    int i = blockIdx.x * CHUNK + threadIdx.x;
    int v = (i < n) ? deg[i] : 0;
    sm[threadIdx.x] = v;
    if (i < n) inv[i] = rsqrtf(v ? (float)v : 1e-6f);
    __syncthreads();
    for (int off = CHUNK / 2; off > 0; off >>= 1) {
        if (threadIdx.x < off) sm[threadIdx.x] += sm[threadIdx.x + off];
        __syncthreads();
    }
    if (threadIdx.x == 0) sums[blockIdx.x] = sm[0];
}

// ---------------- scan phase 2: exclusive scan of chunk sums (1 block) ------
__global__ void scan_sums_kernel(int* __restrict__ sums, int n) {
    __shared__ int sm[CHUNK];
    int t = threadIdx.x;
    int v = (t < n) ? sums[t] : 0;
    sm[t] = v;
    __syncthreads();
    for (int off = 1; off < CHUNK; off <<= 1) {
        int x = (t >= off) ? sm[t - off] : 0;
        __syncthreads();
        sm[t] += x;
        __syncthreads();
    }
    if (t < n) sums[t] = sm[t] - v;  // exclusive
}

// ---------------- scan phase 3: per-chunk exclusive scan -> start ------------
__global__ void chunk_scan_kernel(const int* __restrict__ deg,
                                  const int* __restrict__ chunk_off,
                                  int* __restrict__ start,
                                  int n, int total) {
    __shared__ int sm[CHUNK];
    int i = blockIdx.x * CHUNK + threadIdx.x;
    int t = threadIdx.x;
    int v = (i < n) ? deg[i] : 0;
    sm[t] = v;
    __syncthreads();
    for (int off = 1; off < CHUNK; off <<= 1) {
        int x = (t >= off) ? sm[t - off] : 0;
        __syncthreads();
        sm[t] += x;
        __syncthreads();
    }
    if (i < n) start[i] = chunk_off[blockIdx.x] + sm[t] - v;
    if (i == 0) start[n] = total;
}

// ---------------- fill adjacency (atomic-free, via precomputed ranks) -------
__global__ void fill_kernel(const int* __restrict__ ui,
                            const int* __restrict__ si, int E) {
    int e = blockIdx.x * blockDim.x + threadIdx.x;
    if (e < E) {
        int u = ui[e], s = si[e];
        g_adj_user[g_start_user[u] + g_rank_user[e]] = s;
        g_adj_spot[g_start_spot[s] + g_rank_spot[e]] = u;
    }
}

// ---------------- pull: out[n] = inv_dst[n] * sum_nbr inv_src[nbr]*src[nbr] -
// 16 lanes per node; each lane owns one float4 column. Neighbor indices and
// their inv weights loaded coalesced/cached 16 at a time, broadcast via shfl.
__global__ void pull_kernel(const float4* __restrict__ src,
                            const float* __restrict__ inv_src,
                            const int* __restrict__ adj,
                            const int* __restrict__ start,
                            const float* __restrict__ inv_dst,
                            float4* __restrict__ out, int n_nodes) {
    int node = blockIdx.x * (blockDim.x >> 4) + (threadIdx.x >> 4);
    int lane = threadIdx.x & 15;
    if (node >= n_nodes) return;
    int b = start[node];
    int e = start[node + 1];
    unsigned mask = 0xFFFFu << (threadIdx.x & 16);

    float4 acc = make_float4(0.f, 0.f, 0.f, 0.f);
    int base = b;
    // full 16-neighbor batches: fully unrolled for MLP
    for (; base + 16 <= e; base += 16) {
        int idx = __ldg(&adj[base + lane]);
        float w = __ldg(&inv_src[idx]);
#pragma unroll
        for (int k = 0; k < 16; k++) {
            int s = __shfl_sync(mask, idx, k, 16);
            float ws = __shfl_sync(mask, w, k, 16);
            float4 v = __ldg(&src[s * DV + lane]);
            acc.x = fmaf(v.x, ws, acc.x);
            acc.y = fmaf(v.y, ws, acc.y);
            acc.z = fmaf(v.z, ws, acc.z);
            acc.w = fmaf(v.w, ws, acc.w);
        }
    }
    // remainder
    if (base < e) {
        int cnt = e - base;
        int idx = 0; float w = 0.f;
        if (base + lane < e) {
            idx = __ldg(&adj[base + lane]);
            w = __ldg(&inv_src[idx]);
        }
        for (int k = 0; k < cnt; k++) {
            int s = __shfl_sync(mask, idx, k, 16);
            float ws = __shfl_sync(mask, w, k, 16);
            float4 v = __ldg(&src[s * DV + lane]);
            acc.x = fmaf(v.x, ws, acc.x);
            acc.y = fmaf(v.y, ws, acc.y);
            acc.z = fmaf(v.z, ws, acc.z);
            acc.w = fmaf(v.w, ws, acc.w);
        }
    }
    float m = inv_dst[node];
    acc.x *= m; acc.y *= m; acc.z *= m; acc.w *= m;
    out[node * DV + lane] = acc;
}

extern "C" void kernel_launch(void* const* d_in, const int* in_sizes, int n_in,
                              void* d_out, int out_size) {
    const float4* ux = (const float4*)d_in[0];   // user_x [N_USERS, D]
    const float4* sx = (const float4*)d_in[1];   // spot_x [N_SPOTS, D]
    const int* ui = (const int*)d_in[2];         // user_idx [E]
    const int* si = (const int*)d_in[3];         // spot_idx [E]
    int E = in_sizes[2];

    float* out = (float*)d_out;
    float4* out_user = (float4*)out;                          // [N_USERS, D]
    float4* out_spot = (float4*)(out + (size_t)N_USERS * D);  // [N_SPOTS, D]

    // device-symbol addresses (host side)
    int *p_deg_u, *p_deg_s, *p_start_u, *p_start_s;
    int *p_csum_u, *p_csum_s, *p_adj_u, *p_adj_s;
    float *p_inv_u, *p_inv_s;
    cudaGetSymbolAddress((void**)&p_deg_u, g_deg_user);
    cudaGetSymbolAddress((void**)&p_deg_s, g_deg_spot);
    cudaGetSymbolAddress((void**)&p_start_u, g_start_user);
    cudaGetSymbolAddress((void**)&p_start_s, g_start_spot);
    cudaGetSymbolAddress((void**)&p_csum_u, g_csum_user);
    cudaGetSymbolAddress((void**)&p_csum_s, g_csum_spot);
    cudaGetSymbolAddress((void**)&p_adj_u, g_adj_user);
    cudaGetSymbolAddress((void**)&p_adj_s, g_adj_spot);
    cudaGetSymbolAddress((void**)&p_inv_u, g_inv_user);
    cudaGetSymbolAddress((void**)&p_inv_s, g_inv_spot);

    const int nchunk_u = (N_USERS + CHUNK - 1) / CHUNK;  // 391
    const int nchunk_s = (N_SPOTS + CHUNK - 1) / CHUNK;  // 98

    init_kernel<<<512, 256>>>();
    degree_rank_kernel<<<(E + 255) / 256, 256>>>(ui, si, E);

    // user-side scan (+ fused inv)
    chunk_sum_kernel<<<nchunk_u, CHUNK>>>(p_deg_u, p_csum_u, p_inv_u, N_USERS);
    scan_sums_kernel<<<1, CHUNK>>>(p_csum_u, nchunk_u);
    chunk_scan_kernel<<<nchunk_u, CHUNK>>>(p_deg_u, p_csum_u, p_start_u,
                                           N_USERS, E);
    // spot-side scan (+ fused inv)
    chunk_sum_kernel<<<nchunk_s, CHUNK>>>(p_deg_s, p_csum_s, p_inv_s, N_SPOTS);
    scan_sums_kernel<<<1, CHUNK>>>(p_csum_s, nchunk_s);
    chunk_scan_kernel<<<nchunk_s, CHUNK>>>(p_deg_s, p_csum_s, p_start_s,
                                           N_SPOTS, E);

    fill_kernel<<<(E + 255) / 256, 256>>>(ui, si, E);

    // pulls: 16 nodes per 256-thread block
    pull_kernel<<<(N_USERS + 15) / 16, 256>>>(sx, p_inv_s, p_adj_u, p_start_u,
                                              p_inv_u, out_user, N_USERS);
    pull_kernel<<<(N_SPOTS + 15) / 16, 256>>>(ux, p_inv_u, p_adj_s, p_start_s,
                                              p_inv_s, out_spot, N_SPOTS);
}

// round 6
// speedup vs baseline: 1.5602x; 1.5602x over previous
#include <cuda_runtime.h>
#include <cuda_fp16.h>

#define N_USERS 200000
#define N_SPOTS 50000
#define D 64
#define DV 16           // D/4: float4 per f32 row, uint2 (4 halves) per h16 row
#define MAX_E 3200000
#define CHUNK 512

// ---------------- __device__ scratch (no allocations allowed) ----------------
__device__ int   g_deg_user[N_USERS];
__device__ int   g_deg_spot[N_SPOTS];
__device__ float g_inv_user[N_USERS];
__device__ float g_inv_spot[N_SPOTS];
__device__ int   g_start_user[N_USERS + 1];
__device__ int   g_start_spot[N_SPOTS + 1];
__device__ int   g_adj_user[MAX_E];   // spot neighbors grouped by user
__device__ int   g_adj_spot[MAX_E];   // user neighbors grouped by spot
__device__ int   g_rank_user[MAX_E];  // edge rank within its user's list
__device__ int   g_rank_spot[MAX_E];  // edge rank within its spot's list
__device__ int   g_csum_user[CHUNK];  // chunk partial sums (<=391 used)
__device__ int   g_csum_spot[CHUNK];  // (<=98 used)
__device__ uint2 g_user_h[N_USERS * DV];  // prescaled user msgs, fp16 (8B/lane)
__device__ uint2 g_spot_h[N_SPOTS * DV];  // prescaled spot msgs, fp16

// ---------------- init: zero degree counters ----------------
__global__ void init_kernel() {
    int stride = gridDim.x * blockDim.x;
    int i = blockIdx.x * blockDim.x + threadIdx.x;
    for (int j = i; j < N_USERS; j += stride) g_deg_user[j] = 0;
    for (int j = i; j < N_SPOTS; j += stride) g_deg_spot[j] = 0;
}

// ---------------- degree count + per-edge rank ----------------
__global__ void degree_rank_kernel(const int* __restrict__ ui,
                                   const int* __restrict__ si, int E) {
    int e = blockIdx.x * blockDim.x + threadIdx.x;
    if (e < E) {
        g_rank_user[e] = atomicAdd(&g_deg_user[ui[e]], 1);
        g_rank_spot[e] = atomicAdd(&g_deg_spot[si[e]], 1);
    }
}

// ---------------- scan phase 1: per-chunk sums (+ fused inv = rsqrt(deg)) ----
__global__ void chunk_sum_kernel(const int* __restrict__ deg,
                                 int* __restrict__ sums,
                                 float* __restrict__ inv, int n) {
    __shared__ int sm[CHUNK];
    int i = blockIdx.x * CHUNK + threadIdx.x;
    int v = (i < n) ? deg[i] : 0;
    sm[threadIdx.x] = v;
    if (i < n) inv[i] = rsqrtf(v ? (float)v : 1e-6f);
    __syncthreads();
    for (int off = CHUNK / 2; off > 0; off >>= 1) {
        if (threadIdx.x < off) sm[threadIdx.x] += sm[threadIdx.x + off];
        __syncthreads();
    }
    if (threadIdx.x == 0) sums[blockIdx.x] = sm[0];
}

// ---------------- scan phase 2: exclusive scan of chunk sums (1 block) ------
__global__ void scan_sums_kernel(int* __restrict__ sums, int n) {
    __shared__ int sm[CHUNK];
    int t = threadIdx.x;
    int v = (t < n) ? sums[t] : 0;
    sm[t] = v;
    __syncthreads();
    for (int off = 1; off < CHUNK; off <<= 1) {
        int x = (t >= off) ? sm[t - off] : 0;
        __syncthreads();
        sm[t] += x;
        __syncthreads();
    }
    if (t < n) sums[t] = sm[t] - v;  // exclusive
}

// ---------------- scan phase 3: per-chunk exclusive scan -> start ------------
__global__ void chunk_scan_kernel(const int* __restrict__ deg,
                                  const int* __restrict__ chunk_off,
                                  int* __restrict__ start,
                                  int n, int total) {
    __shared__ int sm[CHUNK];
    int i = blockIdx.x * CHUNK + threadIdx.x;
    int t = threadIdx.x;
    int v = (i < n) ? deg[i] : 0;
    sm[t] = v;
    __syncthreads();
    for (int off = 1; off < CHUNK; off <<= 1) {
        int x = (t >= off) ? sm[t - off] : 0;
        __syncthreads();
        sm[t] += x;
        __syncthreads();
    }
    if (i < n) start[i] = chunk_off[blockIdx.x] + sm[t] - v;
    if (i == 0) start[n] = total;
}

// ---------------- prescale feature tables -> fp16 messages ------------------
__global__ void prescale_kernel(const float4* __restrict__ ux,
                                const float4* __restrict__ sx) {
    int i = blockIdx.x * blockDim.x + threadIdx.x;
    const int nU = N_USERS * DV;
    const int nS = N_SPOTS * DV;
    if (i < nU) {
        float m = g_inv_user[i >> 4];
        float4 v = ux[i];
        __half2 h0 = __floats2half2_rn(v.x * m, v.y * m);
        __half2 h1 = __floats2half2_rn(v.z * m, v.w * m);
        uint2 p;
        p.x = *reinterpret_cast<unsigned*>(&h0);
        p.y = *reinterpret_cast<unsigned*>(&h1);
        g_user_h[i] = p;
    } else if (i < nU + nS) {
        int j = i - nU;
        float m = g_inv_spot[j >> 4];
        float4 v = sx[j];
        __half2 h0 = __floats2half2_rn(v.x * m, v.y * m);
        __half2 h1 = __floats2half2_rn(v.z * m, v.w * m);
        uint2 p;
        p.x = *reinterpret_cast<unsigned*>(&h0);
        p.y = *reinterpret_cast<unsigned*>(&h1);
        g_spot_h[j] = p;
    }
}

// ---------------- fill adjacency (atomic-free, via precomputed ranks) -------
__global__ void fill_kernel(const int* __restrict__ ui,
                            const int* __restrict__ si, int E) {
    int e = blockIdx.x * blockDim.x + threadIdx.x;
    if (e < E) {
        int u = ui[e], s = si[e];
        g_adj_user[g_start_user[u] + g_rank_user[e]] = s;
        g_adj_spot[g_start_spot[s] + g_rank_spot[e]] = u;
    }
}

// ---------------- pull: out[n] = inv_dst[n] * sum_nbr msg_h16[nbr] ----------
// 16 lanes per node; each lane owns 4 columns (uint2 = 4 halves = 8B, so one
// neighbor row = 128B = 1 L1 wavefront). Accumulate fp32.
__global__ void pull_kernel(const uint2* __restrict__ src,
                            const int* __restrict__ adj,
                            const int* __restrict__ start,
                            const float* __restrict__ inv_dst,
                            float4* __restrict__ out, int n_nodes) {
    int node = blockIdx.x * (blockDim.x >> 4) + (threadIdx.x >> 4);
    int lane = threadIdx.x & 15;
    if (node >= n_nodes) return;
    int b = start[node];
    int e = start[node + 1];
    unsigned mask = 0xFFFFu << (threadIdx.x & 16);

    float4 acc = make_float4(0.f, 0.f, 0.f, 0.f);
    int base = b;
    // full 16-neighbor batches: fully unrolled for MLP
    for (; base + 16 <= e; base += 16) {
        int idx = __ldg(&adj[base + lane]);
#pragma unroll
        for (int k = 0; k < 16; k++) {
            int s = __shfl_sync(mask, idx, k, 16);
            uint2 p = __ldg(&src[s * DV + lane]);
            float2 f0 = __half22float2(*reinterpret_cast<__half2*>(&p.x));
            float2 f1 = __half22float2(*reinterpret_cast<__half2*>(&p.y));
            acc.x += f0.x; acc.y += f0.y; acc.z += f1.x; acc.w += f1.y;
        }
    }
    // remainder
    if (base < e) {
        int cnt = e - base;
        int idx = (base + lane < e) ? __ldg(&adj[base + lane]) : 0;
        for (int k = 0; k < cnt; k++) {
            int s = __shfl_sync(mask, idx, k, 16);
            uint2 p = __ldg(&src[s * DV + lane]);
            float2 f0 = __half22float2(*reinterpret_cast<__half2*>(&p.x));
            float2 f1 = __half22float2(*reinterpret_cast<__half2*>(&p.y));
            acc.x += f0.x; acc.y += f0.y; acc.z += f1.x; acc.w += f1.y;
        }
    }
    float m = inv_dst[node];
    acc.x *= m; acc.y *= m; acc.z *= m; acc.w *= m;
    out[node * DV + lane] = acc;
}

extern "C" void kernel_launch(void* const* d_in, const int* in_sizes, int n_in,
                              void* d_out, int out_size) {
    const float4* ux = (const float4*)d_in[0];   // user_x [N_USERS, D]
    const float4* sx = (const float4*)d_in[1];   // spot_x [N_SPOTS, D]
    const int* ui = (const int*)d_in[2];         // user_idx [E]
    const int* si = (const int*)d_in[3];         // spot_idx [E]
    int E = in_sizes[2];

    float* out = (float*)d_out;
    float4* out_user = (float4*)out;                          // [N_USERS, D]
    float4* out_spot = (float4*)(out + (size_t)N_USERS * D);  // [N_SPOTS, D]

    // device-symbol addresses (host side)
    int *p_deg_u, *p_deg_s, *p_start_u, *p_start_s;
    int *p_csum_u, *p_csum_s, *p_adj_u, *p_adj_s;
    float *p_inv_u, *p_inv_s;
    uint2 *p_uh, *p_sh;
    cudaGetSymbolAddress((void**)&p_deg_u, g_deg_user);
    cudaGetSymbolAddress((void**)&p_deg_s, g_deg_spot);
    cudaGetSymbolAddress((void**)&p_start_u, g_start_user);
    cudaGetSymbolAddress((void**)&p_start_s, g_start_spot);
    cudaGetSymbolAddress((void**)&p_csum_u, g_csum_user);
    cudaGetSymbolAddress((void**)&p_csum_s, g_csum_spot);
    cudaGetSymbolAddress((void**)&p_adj_u, g_adj_user);
    cudaGetSymbolAddress((void**)&p_adj_s, g_adj_spot);
    cudaGetSymbolAddress((void**)&p_inv_u, g_inv_user);
    cudaGetSymbolAddress((void**)&p_inv_s, g_inv_spot);
    cudaGetSymbolAddress((void**)&p_uh, g_user_h);
    cudaGetSymbolAddress((void**)&p_sh, g_spot_h);

    const int nchunk_u = (N_USERS + CHUNK - 1) / CHUNK;  // 391
    const int nchunk_s = (N_SPOTS + CHUNK - 1) / CHUNK;  // 98

    init_kernel<<<512, 256>>>();
    degree_rank_kernel<<<(E + 255) / 256, 256>>>(ui, si, E);

    // user-side scan (+ fused inv)
    chunk_sum_kernel<<<nchunk_u, CHUNK>>>(p_deg_u, p_csum_u, p_inv_u, N_USERS);
    scan_sums_kernel<<<1, CHUNK>>>(p_csum_u, nchunk_u);
    chunk_scan_kernel<<<nchunk_u, CHUNK>>>(p_deg_u, p_csum_u, p_start_u,
                                           N_USERS, E);
    // spot-side scan (+ fused inv)
    chunk_sum_kernel<<<nchunk_s, CHUNK>>>(p_deg_s, p_csum_s, p_inv_s, N_SPOTS);
    scan_sums_kernel<<<1, CHUNK>>>(p_csum_s, nchunk_s);
    chunk_scan_kernel<<<nchunk_s, CHUNK>>>(p_deg_s, p_csum_s, p_start_s,
                                           N_SPOTS, E);

    const int n_pre = (N_USERS + N_SPOTS) * DV;
    prescale_kernel<<<(n_pre + 255) / 256, 256>>>(ux, sx);

    fill_kernel<<<(E + 255) / 256, 256>>>(ui, si, E);

    // pulls: 16 nodes per 256-thread block
    pull_kernel<<<(N_USERS + 15) / 16, 256>>>(p_sh, p_adj_u, p_start_u,
                                              p_inv_u, out_user, N_USERS);
    pull_kernel<<<(N_SPOTS + 15) / 16, 256>>>(p_uh, p_adj_s, p_start_s,
                                              p_inv_s, out_spot, N_SPOTS);
}

// round 10
// speedup vs baseline: 1.5742x; 1.0090x over previous
#include <cuda_runtime.h>
#include <cuda_fp16.h>

#define N_USERS 200000
#define N_SPOTS 50000
#define D 64
#define DV 16           // D/4: float4 per f32 row, uint2 (4 halves) per h16 row
#define MAX_E 3200000
#define CHUNK 512
#define NCHUNK_U ((N_USERS + CHUNK - 1) / CHUNK)   // 391
#define NCHUNK_S ((N_SPOTS + CHUNK - 1) / CHUNK)   // 98

// ---------------- __device__ scratch (no allocations allowed) ----------------
__device__ int   g_deg_user[N_USERS];
__device__ int   g_deg_spot[N_SPOTS];
__device__ float g_inv_user[N_USERS];
__device__ float g_inv_spot[N_SPOTS];
__device__ int   g_start_user[N_USERS + 1];
__device__ int   g_start_spot[N_SPOTS + 1];
__device__ int   g_cur_user[N_USERS];
__device__ int   g_cur_spot[N_SPOTS];
__device__ int   g_adj_user[MAX_E];   // spot neighbors grouped by user
__device__ int   g_adj_spot[MAX_E];   // user neighbors grouped by spot
__device__ int   g_csum_user[CHUNK];  // chunk partial sums (391 used)
__device__ int   g_csum_spot[CHUNK];  // (98 used)
__device__ uint2 g_user_h[N_USERS * DV];  // prescaled user msgs, fp16 (8B/lane)
__device__ uint2 g_spot_h[N_SPOTS * DV];  // prescaled spot msgs, fp16

// ---------------- degree count ----------------
__global__ void degree_kernel(const int* __restrict__ ui,
                              const int* __restrict__ si, int E) {
    int e = blockIdx.x * blockDim.x + threadIdx.x;
    if (e < E) {
        atomicAdd(&g_deg_user[ui[e]], 1);
        atomicAdd(&g_deg_spot[si[e]], 1);
    }
}

// ---------------- scan phase 1 (both sides): per-chunk sums + fused rsqrt ---
__global__ void chunk_sum_all_kernel() {
    __shared__ int sm[CHUNK];
    const int* deg;  int* sums;  float* inv;  int n, cb;
    if (blockIdx.x < NCHUNK_U) {
        deg = g_deg_user; sums = g_csum_user; inv = g_inv_user;
        n = N_USERS; cb = blockIdx.x;
    } else {
        deg = g_deg_spot; sums = g_csum_spot; inv = g_inv_spot;
        n = N_SPOTS; cb = blockIdx.x - NCHUNK_U;
    }
    int i = cb * CHUNK + threadIdx.x;
    int v = (i < n) ? deg[i] : 0;
    sm[threadIdx.x] = v;
    if (i < n) inv[i] = rsqrtf(v ? (float)v : 1e-6f);
    __syncthreads();
    for (int off = CHUNK / 2; off > 0; off >>= 1) {
        if (threadIdx.x < off) sm[threadIdx.x] += sm[threadIdx.x + off];
        __syncthreads();
    }
    if (threadIdx.x == 0) sums[cb] = sm[0];
}

// ---------------- scan phase 2: exclusive scan of both chunk-sum arrays -----
__global__ void scan_sums_all_kernel() {
    __shared__ int sm[CHUNK];
    int t = threadIdx.x;
    // user side
    {
        int v = (t < NCHUNK_U) ? g_csum_user[t] : 0;
        sm[t] = v;
        __syncthreads();
        for (int off = 1; off < CHUNK; off <<= 1) {
            int x = (t >= off) ? sm[t - off] : 0;
            __syncthreads();
            sm[t] += x;
            __syncthreads();
        }
        if (t < NCHUNK_U) g_csum_user[t] = sm[t] - v;
        __syncthreads();
    }
    // spot side
    {
        int v = (t < NCHUNK_S) ? g_csum_spot[t] : 0;
        sm[t] = v;
        __syncthreads();
        for (int off = 1; off < CHUNK; off <<= 1) {
            int x = (t >= off) ? sm[t - off] : 0;
            __syncthreads();
            sm[t] += x;
            __syncthreads();
        }
        if (t < NCHUNK_S) g_csum_spot[t] = sm[t] - v;
    }
}

// ---------------- scan phase 3 (both sides): chunk scan -> start + cursor ---
__global__ void chunk_scan_all_kernel(int E) {
    __shared__ int sm[CHUNK];
    const int* deg;  const int* coff;  int* start;  int* cur;  int n, cb;
    if (blockIdx.x < NCHUNK_U) {
        deg = g_deg_user; coff = g_csum_user; start = g_start_user;
        cur = g_cur_user; n = N_USERS; cb = blockIdx.x;
    } else {
        deg = g_deg_spot; coff = g_csum_spot; start = g_start_spot;
        cur = g_cur_spot; n = N_SPOTS; cb = blockIdx.x - NCHUNK_U;
    }
    int i = cb * CHUNK + threadIdx.x;
    int t = threadIdx.x;
    int v = (i < n) ? deg[i] : 0;
    sm[t] = v;
    __syncthreads();
    for (int off = 1; off < CHUNK; off <<= 1) {
        int x = (t >= off) ? sm[t - off] : 0;
        __syncthreads();
        sm[t] += x;
        __syncthreads();
    }
    if (i < n) {
        int ex = coff[cb] + sm[t] - v;
        start[i] = ex;
        cur[i]   = ex;
    }
    if (i == 0) start[n] = E;
}

// ---------------- fused fill (cursor atomics) + prescale --------------------
__global__ void fill_prescale_kernel(const int* __restrict__ ui,
                                     const int* __restrict__ si,
                                     const float4* __restrict__ ux,
                                     const float4* __restrict__ sx,
                                     int E, int nb_fill) {
    if ((int)blockIdx.x < nb_fill) {
        int e = blockIdx.x * blockDim.x + threadIdx.x;
        if (e < E) {
            int u = ui[e], s = si[e];
            int pu = atomicAdd(&g_cur_user[u], 1);
            g_adj_user[pu] = s;
            int ps = atomicAdd(&g_cur_spot[s], 1);
            g_adj_spot[ps] = u;
        }
    } else {
        int i = (blockIdx.x - nb_fill) * blockDim.x + threadIdx.x;
        const int nU = N_USERS * DV;
        const int nS = N_SPOTS * DV;
        if (i < nU) {
            float m = g_inv_user[i >> 4];
            float4 v = ux[i];
            __half2 h0 = __floats2half2_rn(v.x * m, v.y * m);
            __half2 h1 = __floats2half2_rn(v.z * m, v.w * m);
            uint2 p;
            p.x = *reinterpret_cast<unsigned*>(&h0);
            p.y = *reinterpret_cast<unsigned*>(&h1);
            g_user_h[i] = p;
        } else if (i < nU + nS) {
            int j = i - nU;
            float m = g_inv_spot[j >> 4];
            float4 v = sx[j];
            __half2 h0 = __floats2half2_rn(v.x * m, v.y * m);
            __half2 h1 = __floats2half2_rn(v.z * m, v.w * m);
            uint2 p;
            p.x = *reinterpret_cast<unsigned*>(&h0);
            p.y = *reinterpret_cast<unsigned*>(&h1);
            g_spot_h[j] = p;
        }
    }
}

// ---------------- pull body: out[n] = inv_dst[n] * sum_nbr msg_h16[nbr] -----
__device__ __forceinline__ void pull_node(const uint2* __restrict__ src,
                                          const int* __restrict__ adj,
                                          const int* __restrict__ start,
                                          const float* __restrict__ inv_dst,
                                          float4* __restrict__ out,
                                          int node, int lane, unsigned mask) {
    int b = start[node];
    int e = start[node + 1];
    float4 acc = make_float4(0.f, 0.f, 0.f, 0.f);
    int base = b;
    for (; base + 16 <= e; base += 16) {
        int idx = __ldg(&adj[base + lane]);
#pragma unroll
        for (int k = 0; k < 16; k++) {
            int s = __shfl_sync(mask, idx, k, 16);
            uint2 p = __ldg(&src[s * DV + lane]);
            float2 f0 = __half22float2(*reinterpret_cast<__half2*>(&p.x));
            float2 f1 = __half22float2(*reinterpret_cast<__half2*>(&p.y));
            acc.x += f0.x; acc.y += f0.y; acc.z += f1.x; acc.w += f1.y;
        }
    }
    if (base < e) {
        int cnt = e - base;
        int idx = (base + lane < e) ? __ldg(&adj[base + lane]) : 0;
        for (int k = 0; k < cnt; k++) {
            int s = __shfl_sync(mask, idx, k, 16);
            uint2 p = __ldg(&src[s * DV + lane]);
            float2 f0 = __half22float2(*reinterpret_cast<__half2*>(&p.x));
            float2 f1 = __half22float2(*reinterpret_cast<__half2*>(&p.y));
            acc.x += f0.x; acc.y += f0.y; acc.z += f1.x; acc.w += f1.y;
        }
    }
    float m = inv_dst[node];
    acc.x *= m; acc.y *= m; acc.z *= m; acc.w *= m;
    out[node * DV + lane] = acc;
}

// ---------------- fused pulls (both directions in one grid) -----------------
__global__ void pull_all_kernel(float4* __restrict__ out_user,
                                float4* __restrict__ out_spot,
                                int nb_user) {
    int lane = threadIdx.x & 15;
    unsigned mask = 0xFFFFu << (threadIdx.x & 16);
    int grp = threadIdx.x >> 4;  // 0..15
    if ((int)blockIdx.x < nb_user) {
        int node = blockIdx.x * 16 + grp;
        if (node < N_USERS)
            pull_node(g_spot_h, g_adj_user, g_start_user, g_inv_user,
                      out_user, node, lane, mask);
    } else {
        int node = (blockIdx.x - nb_user) * 16 + grp;
        if (node < N_SPOTS)
            pull_node(g_user_h, g_adj_spot, g_start_spot, g_inv_spot,
                      out_spot, node, lane, mask);
    }
}

extern "C" void kernel_launch(void* const* d_in, const int* in_sizes, int n_in,
                              void* d_out, int out_size) {
    const float4* ux = (const float4*)d_in[0];   // user_x [N_USERS, D]
    const float4* sx = (const float4*)d_in[1];   // spot_x [N_SPOTS, D]
    const int* ui = (const int*)d_in[2];         // user_idx [E]
    const int* si = (const int*)d_in[3];         // spot_idx [E]
    int E = in_sizes[2];

    float* out = (float*)d_out;
    float4* out_user = (float4*)out;                          // [N_USERS, D]
    float4* out_spot = (float4*)(out + (size_t)N_USERS * D);  // [N_SPOTS, D]

    int *p_deg_u, *p_deg_s;
    cudaGetSymbolAddress((void**)&p_deg_u, g_deg_user);
    cudaGetSymbolAddress((void**)&p_deg_s, g_deg_spot);

    cudaMemsetAsync(p_deg_u, 0, N_USERS * sizeof(int));
    cudaMemsetAsync(p_deg_s, 0, N_SPOTS * sizeof(int));

    degree_kernel<<<(E + 255) / 256, 256>>>(ui, si, E);

    chunk_sum_all_kernel<<<NCHUNK_U + NCHUNK_S, CHUNK>>>();
    scan_sums_all_kernel<<<1, CHUNK>>>();
    chunk_scan_all_kernel<<<NCHUNK_U + NCHUNK_S, CHUNK>>>(E);

    int nb_fill = (E + 255) / 256;                       // 12500
    int nb_pre  = ((N_USERS + N_SPOTS) * DV + 255) / 256; // 15625
    fill_prescale_kernel<<<nb_fill + nb_pre, 256>>>(ui, si, ux, sx, E, nb_fill);

    int nb_user = (N_USERS + 15) / 16;  // 12500
    int nb_spot = (N_SPOTS + 15) / 16;  // 3125
    pull_all_kernel<<<nb_user + nb_spot, 256>>>(out_user, out_spot, nb_user);
}